// round 3
// baseline (speedup 1.0000x reference)
#include <cuda_runtime.h>
#include <cuda_bf16.h>

#define NMASKS 128
#define W      1024
#define TILE_ROWS 64
#define TILES_PER_MASK (W / TILE_ROWS)       // 16
#define NBLOCKS (NMASKS * TILES_PER_MASK)    // 2048
#define HALO (TILE_ROWS + 2)                 // 66
#define STRIDE 35                            // gcd(35,32)=1 -> conflict-free

__device__ unsigned g_pA[NBLOCKS];
__device__ unsigned g_pC[NBLOCKS];
__device__ unsigned g_pP[NBLOCKS];
__device__ unsigned g_ctr = 0;

__device__ __forceinline__ void csa(unsigned a, unsigned b, unsigned c,
                                    unsigned &s, unsigned &cy) {
    unsigned t = a ^ b;
    s  = t ^ c;
    cy = (a & b) | (t & c);
}

__global__ __launch_bounds__(256, 4)
void prior_kernel(const float* __restrict__ masks, float* __restrict__ out) {
    // Interleaved-bitplane packed rows. Group g (128 cols) occupies slots
    // 1+4g .. 4+4g: plane k bit l = column 128g + 4l + k.
    // Guard slot 0  == "plane3 of group -1" (zero)
    // Guard slot 33 == "plane0 of group 8"  (zero)
    __shared__ unsigned srows[HALO][STRIDE];
    __shared__ unsigned red[8][3];
    __shared__ int is_last;

    const int bid  = blockIdx.x;
    const int mask = bid >> 4;           // 16 tiles per mask
    const int tile = bid & 15;
    const int r0   = tile * TILE_ROWS;
    const float4* __restrict__ base =
        (const float4*)(masks + (size_t)mask * (size_t)(W * W));

    const int tid  = threadIdx.x;
    const int lane = tid & 31;
    const int wp   = tid >> 5;           // 8 warps

    // ---- pack phase: float4 loads, 4 ballots -> 4 interleaved bitplanes ----
    for (int k = wp; k < HALO; k += 8) {
        int gr = r0 - 1 + k;
        if ((unsigned)gr >= (unsigned)W) {
            srows[k][lane] = 0u;
            if (lane < STRIDE - 32) srows[k][32 + lane] = 0u;
        } else {
            const float4* __restrict__ rowp = base + (size_t)gr * (W / 4);
            if (lane == 0) { srows[k][0] = 0u; srows[k][33] = 0u; }
            #pragma unroll
            for (int it = 0; it < 8; it++) {
                float4 v = rowp[it * 32 + lane];
                unsigned p0 = __ballot_sync(0xffffffffu, v.x > 0.0f);
                unsigned p1 = __ballot_sync(0xffffffffu, v.y > 0.0f);
                unsigned p2 = __ballot_sync(0xffffffffu, v.z > 0.0f);
                unsigned p3 = __ballot_sync(0xffffffffu, v.w > 0.0f);
                unsigned mine = (lane == 0) ? p0 : (lane == 1) ? p1
                              : (lane == 2) ? p2 : p3;
                if (lane < 4) srows[k][1 + 4 * it + lane] = mine;
            }
        }
    }
    __syncthreads();

    // ---- compute phase: 64 rows x 8 groups = 512 group-tasks, 2/thread ----
    unsigned accA = 0, accC = 0, accP = 0;
    #pragma unroll
    for (int i = 0; i < 2; i++) {
        int id = tid + 256 * i;
        int g  = id & 7;                 // group 0..7
        int r  = id >> 3;                // row 0..63 -> smem rows r, r+1, r+2
        const unsigned* __restrict__ Tr = srows[r];
        const unsigned* __restrict__ Mr = srows[r + 1];
        const unsigned* __restrict__ Br = srows[r + 2];
        int s = 1 + 4 * g;

        unsigned T[4], M[4], B[4];
        #pragma unroll
        for (int k = 0; k < 4; k++) { T[k] = Tr[s + k]; M[k] = Mr[s + k]; B[k] = Br[s + k]; }
        unsigned Tp3 = Tr[s - 1], Mp3 = Mr[s - 1], Bp3 = Br[s - 1]; // plane3 of g-1
        unsigned Tn0 = Tr[s + 4], Mn0 = Mr[s + 4], Bn0 = Br[s + 4]; // plane0 of g+1

        // shifted planes for the group-boundary columns
        unsigned TSL = (T[3] << 1) | (Tp3 >> 31), TSR = (T[0] >> 1) | (Tn0 << 31);
        unsigned MSL = (M[3] << 1) | (Mp3 >> 31), MSR = (M[0] >> 1) | (Mn0 << 31);
        unsigned BSL = (B[3] << 1) | (Bp3 >> 31), BSR = (B[0] >> 1) | (Bn0 << 31);

        #pragma unroll
        for (int k = 0; k < 4; k++) {
            unsigned tl = (k > 0) ? T[k - 1] : TSL;
            unsigned ml = (k > 0) ? M[k - 1] : MSL;
            unsigned bl = (k > 0) ? B[k - 1] : BSL;
            unsigned tr = (k < 3) ? T[k + 1] : TSR;
            unsigned mr = (k < 3) ? M[k + 1] : MSR;
            unsigned br = (k < 3) ? B[k + 1] : BSR;
            unsigned tt = T[k], bot = B[k], mid = M[k];

            // CSA tree: per-bit neighbor count (0..8) as bitplanes b0..b3
            unsigned s1, c1, s2, c2, s3, c3;
            csa(tl, tt, tr, s1, c1);
            csa(ml, mr, bl, s2, c2);
            csa(bot, br, s1, s3, c3);
            unsigned s4 = s2 ^ s3, c4 = s2 & s3;
            unsigned u1, v1;
            csa(c1, c2, c3, u1, v1);
            unsigned u2 = u1 ^ c4, v2 = u1 & c4;
            unsigned b0 = s4, b1 = u2, b2 = v1 ^ v2, b3 = v1 & v2;

            accA += __popc(mid);

            unsigned conn = __popc(b0 & mid) + 2u * __popc(b1 & mid)
                          + 4u * __popc(b2 & mid) + 8u * __popc(b3 & mid);
            unsigned tot  = __popc(b0) + 2u * __popc(b1)
                          + 4u * __popc(b2) + 8u * __popc(b3);
            unsigned perim = (tot - conn)
                           + 4u * __popc(b3 & mid)
                           + 2u * __popc(b2 & b1 & mid)
                           +      __popc(b2 & b0 & mid);

            accC += conn;
            accP += perim;
        }
    }

    // ---- block reduction (exact integers) ----
    accA = __reduce_add_sync(0xffffffffu, accA);
    accC = __reduce_add_sync(0xffffffffu, accC);
    accP = __reduce_add_sync(0xffffffffu, accP);
    if (lane == 0) { red[wp][0] = accA; red[wp][1] = accC; red[wp][2] = accP; }
    __syncthreads();

    if (tid == 0) {
        unsigned a = 0, c = 0, p = 0;
        #pragma unroll
        for (int w2 = 0; w2 < 8; w2++) { a += red[w2][0]; c += red[w2][1]; p += red[w2][2]; }
        g_pA[bid] = a; g_pC[bid] = c; g_pP[bid] = p;
        __threadfence();
        unsigned ticket = atomicInc(&g_ctr, NBLOCKS - 1);  // wraps to 0 -> replayable
        is_last = (ticket == NBLOCKS - 1);
    }
    __syncthreads();

    // ---- last block: final reduction + scoring ----
    if (is_last && tid < NMASKS) {
        volatile unsigned* vA = g_pA;
        volatile unsigned* vC = g_pC;
        volatile unsigned* vP = g_pP;
        unsigned a = 0, c = 0, p = 0;
        #pragma unroll
        for (int t2 = 0; t2 < TILES_PER_MASK; t2++) {
            int j = tid * TILES_PER_MASK + t2;
            a += vA[j]; c += vC[j]; p += vP[j];
        }
        float area  = (float)a;
        float conn  = (float)c;
        float perim = (float)p;

        float safe_area  = (area > 0.0f) ? area : 1.0f;
        float area_ratio = area / (float)(W * W);
        float area_score = (area_ratio >= 0.001f && area_ratio <= 0.5f) ? 1.0f : 0.1f;

        float comp_score = (conn > 0.0f)
            ? fminf(1.0f, 10.0f / (conn / safe_area + 1e-6f))
            : 0.1f;

        float par = perim / safe_area;
        float shape_score = (area > 0.0f)
            ? ((par <= 100.0f) ? 1.0f : fmaxf(0.1f, 100.0f / (par + 1e-6f)))
            : 0.1f;

        float validity = 0.4f * area_score + 0.3f * comp_score + 0.3f * shape_score;
        out[tid] = fmaxf(0.05f, validity);
    }
}

extern "C" void kernel_launch(void* const* d_in, const int* in_sizes, int n_in,
                              void* d_out, int out_size) {
    const float* masks = (const float*)d_in[0];
    float* out = (float*)d_out;
    (void)in_sizes; (void)n_in; (void)out_size;

    prior_kernel<<<NBLOCKS, 256>>>(masks, out);
}

// round 4
// speedup vs baseline: 2.7009x; 2.7009x over previous
#include <cuda_runtime.h>
#include <cuda_bf16.h>

#define NMASKS 128
#define W      1024
#define TILE_ROWS 64
#define TILES_PER_MASK (W / TILE_ROWS)       // 16
#define NBLOCKS (NMASKS * TILES_PER_MASK)    // 2048
#define HALO (TILE_ROWS + 2)                 // 66
#define STRIDE 35                            // gcd(35,32)=1 -> conflict-free

__device__ unsigned g_pA[NBLOCKS];
__device__ unsigned g_pC[NBLOCKS];
__device__ unsigned g_pP[NBLOCKS];
__device__ unsigned g_ctr = 0;

__device__ __forceinline__ void csa(unsigned a, unsigned b, unsigned c,
                                    unsigned &s, unsigned &cy) {
    unsigned t = a ^ b;
    s  = t ^ c;
    cy = (a & b) | (t & c);
}

__global__ __launch_bounds__(256, 5)
void prior_kernel(const float* __restrict__ masks, float* __restrict__ out) {
    // Interleaved-bitplane packed rows. Group g (128 cols) occupies slots
    // 1+4g .. 4+4g: plane k bit l = column 128g + 4l + k.
    // Guard slot 0  == "plane3 of group -1" (zero)
    // Guard slot 33 == "plane0 of group 8"  (zero)
    __shared__ unsigned srows[HALO][STRIDE];
    __shared__ unsigned red[8][3];
    __shared__ int is_last;

    const int bid  = blockIdx.x;
    const int mask = bid >> 4;           // 16 tiles per mask
    const int tile = bid & 15;
    const int r0   = tile * TILE_ROWS;
    const float4* __restrict__ base =
        (const float4*)(masks + (size_t)mask * (size_t)(W * W));

    const int tid  = threadIdx.x;
    const int lane = tid & 31;
    const int wp   = tid >> 5;           // 8 warps

    // ---- pack phase: batched float4 loads (forced MLP=8), then ballots ----
    for (int k = wp; k < HALO; k += 8) {
        int gr = r0 - 1 + k;
        if ((unsigned)gr >= (unsigned)W) {
            srows[k][lane] = 0u;
            if (lane < STRIDE - 32) srows[k][32 + lane] = 0u;
        } else {
            const float4* __restrict__ rowp = base + (size_t)gr * (W / 4);
            // Batch ALL loads for this row before any ballot: 8 LDG.128 in flight.
            float4 v[8];
            #pragma unroll
            for (int it = 0; it < 8; it++) v[it] = rowp[it * 32 + lane];
            if (lane == 0) { srows[k][0] = 0u; srows[k][33] = 0u; }
            #pragma unroll
            for (int it = 0; it < 8; it++) {
                unsigned p0 = __ballot_sync(0xffffffffu, v[it].x > 0.0f);
                unsigned p1 = __ballot_sync(0xffffffffu, v[it].y > 0.0f);
                unsigned p2 = __ballot_sync(0xffffffffu, v[it].z > 0.0f);
                unsigned p3 = __ballot_sync(0xffffffffu, v[it].w > 0.0f);
                unsigned mine = (lane == 0) ? p0 : (lane == 1) ? p1
                              : (lane == 2) ? p2 : p3;
                if (lane < 4) srows[k][1 + 4 * it + lane] = mine;
            }
        }
    }
    __syncthreads();

    // ---- compute phase: 64 rows x 8 groups = 512 group-tasks, 2/thread ----
    unsigned accA = 0, accC = 0, accP = 0;
    #pragma unroll 1
    for (int i = 0; i < 2; i++) {
        int id = tid + 256 * i;
        int g  = id & 7;                 // group 0..7
        int r  = id >> 3;                // row 0..63 -> smem rows r, r+1, r+2
        const unsigned* __restrict__ Tr = srows[r];
        const unsigned* __restrict__ Mr = srows[r + 1];
        const unsigned* __restrict__ Br = srows[r + 2];
        int s = 1 + 4 * g;

        unsigned T[4], M[4], B[4];
        #pragma unroll
        for (int k = 0; k < 4; k++) { T[k] = Tr[s + k]; M[k] = Mr[s + k]; B[k] = Br[s + k]; }
        unsigned Tp3 = Tr[s - 1], Mp3 = Mr[s - 1], Bp3 = Br[s - 1]; // plane3 of g-1
        unsigned Tn0 = Tr[s + 4], Mn0 = Mr[s + 4], Bn0 = Br[s + 4]; // plane0 of g+1

        // shifted planes for the group-boundary columns
        unsigned TSL = (T[3] << 1) | (Tp3 >> 31), TSR = (T[0] >> 1) | (Tn0 << 31);
        unsigned MSL = (M[3] << 1) | (Mp3 >> 31), MSR = (M[0] >> 1) | (Mn0 << 31);
        unsigned BSL = (B[3] << 1) | (Bp3 >> 31), BSR = (B[0] >> 1) | (Bn0 << 31);

        #pragma unroll
        for (int k = 0; k < 4; k++) {
            unsigned tl = (k > 0) ? T[k - 1] : TSL;
            unsigned ml = (k > 0) ? M[k - 1] : MSL;
            unsigned bl = (k > 0) ? B[k - 1] : BSL;
            unsigned tr = (k < 3) ? T[k + 1] : TSR;
            unsigned mr = (k < 3) ? M[k + 1] : MSR;
            unsigned br = (k < 3) ? B[k + 1] : BSR;
            unsigned tt = T[k], bot = B[k], mid = M[k];

            // CSA tree: per-bit neighbor count (0..8) as bitplanes b0..b3
            unsigned s1, c1, s2, c2, s3, c3;
            csa(tl, tt, tr, s1, c1);
            csa(ml, mr, bl, s2, c2);
            csa(bot, br, s1, s3, c3);
            unsigned s4 = s2 ^ s3, c4 = s2 & s3;
            unsigned u1, v1;
            csa(c1, c2, c3, u1, v1);
            unsigned u2 = u1 ^ c4, v2 = u1 & c4;
            unsigned b0 = s4, b1 = u2, b2 = v1 ^ v2, b3 = v1 & v2;

            accA += __popc(mid);

            unsigned conn = __popc(b0 & mid) + 2u * __popc(b1 & mid)
                          + 4u * __popc(b2 & mid) + 8u * __popc(b3 & mid);
            unsigned tot  = __popc(b0) + 2u * __popc(b1)
                          + 4u * __popc(b2) + 8u * __popc(b3);
            unsigned perim = (tot - conn)
                           + 4u * __popc(b3 & mid)
                           + 2u * __popc(b2 & b1 & mid)
                           +      __popc(b2 & b0 & mid);

            accC += conn;
            accP += perim;
        }
    }

    // ---- block reduction (exact integers) ----
    accA = __reduce_add_sync(0xffffffffu, accA);
    accC = __reduce_add_sync(0xffffffffu, accC);
    accP = __reduce_add_sync(0xffffffffu, accP);
    if (lane == 0) { red[wp][0] = accA; red[wp][1] = accC; red[wp][2] = accP; }
    __syncthreads();

    if (tid == 0) {
        unsigned a = 0, c = 0, p = 0;
        #pragma unroll
        for (int w2 = 0; w2 < 8; w2++) { a += red[w2][0]; c += red[w2][1]; p += red[w2][2]; }
        g_pA[bid] = a; g_pC[bid] = c; g_pP[bid] = p;
        __threadfence();
        unsigned ticket = atomicInc(&g_ctr, NBLOCKS - 1);  // wraps to 0 -> replayable
        is_last = (ticket == NBLOCKS - 1);
    }
    __syncthreads();

    // ---- last block: final reduction + scoring ----
    if (is_last && tid < NMASKS) {
        volatile unsigned* vA = g_pA;
        volatile unsigned* vC = g_pC;
        volatile unsigned* vP = g_pP;
        unsigned a = 0, c = 0, p = 0;
        #pragma unroll
        for (int t2 = 0; t2 < TILES_PER_MASK; t2++) {
            int j = tid * TILES_PER_MASK + t2;
            a += vA[j]; c += vC[j]; p += vP[j];
        }
        float area  = (float)a;
        float conn  = (float)c;
        float perim = (float)p;

        float safe_area  = (area > 0.0f) ? area : 1.0f;
        float area_ratio = area / (float)(W * W);
        float area_score = (area_ratio >= 0.001f && area_ratio <= 0.5f) ? 1.0f : 0.1f;

        float comp_score = (conn > 0.0f)
            ? fminf(1.0f, 10.0f / (conn / safe_area + 1e-6f))
            : 0.1f;

        float par = perim / safe_area;
        float shape_score = (area > 0.0f)
            ? ((par <= 100.0f) ? 1.0f : fmaxf(0.1f, 100.0f / (par + 1e-6f)))
            : 0.1f;

        float validity = 0.4f * area_score + 0.3f * comp_score + 0.3f * shape_score;
        out[tid] = fmaxf(0.05f, validity);
    }
}

extern "C" void kernel_launch(void* const* d_in, const int* in_sizes, int n_in,
                              void* d_out, int out_size) {
    const float* masks = (const float*)d_in[0];
    float* out = (float*)d_out;
    (void)in_sizes; (void)n_in; (void)out_size;

    prior_kernel<<<NBLOCKS, 256>>>(masks, out);
}

// round 5
// speedup vs baseline: 2.7541x; 1.0197x over previous
#include <cuda_runtime.h>
#include <cuda_bf16.h>

#define NMASKS 128
#define W      1024
#define TILE_ROWS 62
#define TILES_PER_MASK 17                    // 16 x 62 rows + 1 x 32 rows
#define NBLOCKS (NMASKS * TILES_PER_MASK)    // 2176
#define HALO_MAX 64                          // 62 + 2 -> exactly 8 iters/warp
#define STRIDE 35                            // gcd(35,32)=1 -> conflict-free

__device__ unsigned g_pA[NBLOCKS];
__device__ unsigned g_pC[NBLOCKS];
__device__ unsigned g_pP[NBLOCKS];
__device__ unsigned g_ctr = 0;

__device__ __forceinline__ void csa(unsigned a, unsigned b, unsigned c,
                                    unsigned &s, unsigned &cy) {
    unsigned t = a ^ b;
    s  = t ^ c;
    cy = (a & b) | (t & c);
}

__global__ __launch_bounds__(256, 5)
void prior_kernel(const float* __restrict__ masks, float* __restrict__ out) {
    // Interleaved-bitplane packed rows. Group g (128 cols) occupies slots
    // 1+4g .. 4+4g: plane k bit l = column 128g + 4l + k.
    // Guard slot 0  == "plane3 of group -1" (zero)
    // Guard slot 33 == "plane0 of group 8"  (zero)
    __shared__ unsigned srows[HALO_MAX][STRIDE];
    __shared__ unsigned red[8][3];
    __shared__ int is_last;

    const int bid  = blockIdx.x;
    const int mask = bid / TILES_PER_MASK;
    const int tile = bid - mask * TILES_PER_MASK;
    const int r0   = tile * TILE_ROWS;                      // 0..992
    const int rows = (tile < 16) ? TILE_ROWS : (W - 16 * TILE_ROWS);  // 62 or 32
    const int halo = rows + 2;
    const float4* __restrict__ base =
        (const float4*)(masks + (size_t)mask * (size_t)(W * W));

    const int tid  = threadIdx.x;
    const int lane = tid & 31;
    const int wp   = tid >> 5;           // 8 warps

    // guard-word init hoisted out of the hot loop (disjoint slots, covered by
    // the single __syncthreads below)
    for (int j = tid; j < HALO_MAX; j += 256) {
        srows[j][0] = 0u;
        srows[j][33] = 0u;
        srows[j][34] = 0u;
    }

    // ---- pack phase: batched float4 loads (forced MLP=8), then ballots ----
    // halo rows divide evenly: 64/8 = 8 iterations for every warp (full tiles)
    for (int k = wp; k < halo; k += 8) {
        int gr = r0 - 1 + k;
        if ((unsigned)gr >= (unsigned)W) {
            srows[k][lane] = 0u;
        } else {
            const float4* __restrict__ rowp = base + (size_t)gr * (W / 4);
            // Batch ALL loads for this row before any ballot: 8 LDG.128 in flight.
            float4 v[8];
            #pragma unroll
            for (int it = 0; it < 8; it++) v[it] = rowp[it * 32 + lane];
            #pragma unroll
            for (int it = 0; it < 8; it++) {
                unsigned p0 = __ballot_sync(0xffffffffu, v[it].x > 0.0f);
                unsigned p1 = __ballot_sync(0xffffffffu, v[it].y > 0.0f);
                unsigned p2 = __ballot_sync(0xffffffffu, v[it].z > 0.0f);
                unsigned p3 = __ballot_sync(0xffffffffu, v[it].w > 0.0f);
                unsigned mine = (lane == 0) ? p0 : (lane == 1) ? p1
                              : (lane == 2) ? p2 : p3;
                if (lane < 4) srows[k][1 + 4 * it + lane] = mine;
            }
        }
    }
    __syncthreads();

    // ---- compute phase: rows x 8 groups tasks, 256 threads ----
    unsigned accA = 0, accC = 0, accP = 0;
    const int ntasks = rows * 8;         // 496 or 256
    #pragma unroll 1
    for (int base_t = 0; base_t < ntasks; base_t += 256) {
        int id = tid + base_t;
        if (id >= ntasks) break;
        int g  = id & 7;                 // group 0..7
        int r  = id >> 3;                // row -> smem rows r, r+1, r+2
        const unsigned* __restrict__ Tr = srows[r];
        const unsigned* __restrict__ Mr = srows[r + 1];
        const unsigned* __restrict__ Br = srows[r + 2];
        int s = 1 + 4 * g;

        unsigned T[4], M[4], B[4];
        #pragma unroll
        for (int k = 0; k < 4; k++) { T[k] = Tr[s + k]; M[k] = Mr[s + k]; B[k] = Br[s + k]; }
        unsigned Tp3 = Tr[s - 1], Mp3 = Mr[s - 1], Bp3 = Br[s - 1]; // plane3 of g-1
        unsigned Tn0 = Tr[s + 4], Mn0 = Mr[s + 4], Bn0 = Br[s + 4]; // plane0 of g+1

        // shifted planes for the group-boundary columns
        unsigned TSL = (T[3] << 1) | (Tp3 >> 31), TSR = (T[0] >> 1) | (Tn0 << 31);
        unsigned MSL = (M[3] << 1) | (Mp3 >> 31), MSR = (M[0] >> 1) | (Mn0 << 31);
        unsigned BSL = (B[3] << 1) | (Bp3 >> 31), BSR = (B[0] >> 1) | (Bn0 << 31);

        #pragma unroll
        for (int k = 0; k < 4; k++) {
            unsigned tl = (k > 0) ? T[k - 1] : TSL;
            unsigned ml = (k > 0) ? M[k - 1] : MSL;
            unsigned bl = (k > 0) ? B[k - 1] : BSL;
            unsigned tr = (k < 3) ? T[k + 1] : TSR;
            unsigned mr = (k < 3) ? M[k + 1] : MSR;
            unsigned br = (k < 3) ? B[k + 1] : BSR;
            unsigned tt = T[k], bot = B[k], mid = M[k];

            // CSA tree: per-bit neighbor count (0..8) as bitplanes b0..b3
            unsigned s1, c1, s2, c2, s3, c3;
            csa(tl, tt, tr, s1, c1);
            csa(ml, mr, bl, s2, c2);
            csa(bot, br, s1, s3, c3);
            unsigned s4 = s2 ^ s3, c4 = s2 & s3;
            unsigned u1, v1;
            csa(c1, c2, c3, u1, v1);
            unsigned u2 = u1 ^ c4, v2 = u1 & c4;
            unsigned b0 = s4, b1 = u2, b2 = v1 ^ v2, b3 = v1 & v2;

            accA += __popc(mid);

            unsigned conn = __popc(b0 & mid) + 2u * __popc(b1 & mid)
                          + 4u * __popc(b2 & mid) + 8u * __popc(b3 & mid);
            unsigned tot  = __popc(b0) + 2u * __popc(b1)
                          + 4u * __popc(b2) + 8u * __popc(b3);
            unsigned perim = (tot - conn)
                           + 4u * __popc(b3 & mid)
                           + 2u * __popc(b2 & b1 & mid)
                           +      __popc(b2 & b0 & mid);

            accC += conn;
            accP += perim;
        }
    }

    // ---- block reduction (exact integers) ----
    accA = __reduce_add_sync(0xffffffffu, accA);
    accC = __reduce_add_sync(0xffffffffu, accC);
    accP = __reduce_add_sync(0xffffffffu, accP);
    if (lane == 0) { red[wp][0] = accA; red[wp][1] = accC; red[wp][2] = accP; }
    __syncthreads();

    if (tid == 0) {
        unsigned a = 0, c = 0, p = 0;
        #pragma unroll
        for (int w2 = 0; w2 < 8; w2++) { a += red[w2][0]; c += red[w2][1]; p += red[w2][2]; }
        g_pA[bid] = a; g_pC[bid] = c; g_pP[bid] = p;
        __threadfence();
        unsigned ticket = atomicInc(&g_ctr, NBLOCKS - 1);  // wraps to 0 -> replayable
        is_last = (ticket == NBLOCKS - 1);
    }
    __syncthreads();

    // ---- last block: final reduction + scoring ----
    if (is_last && tid < NMASKS) {
        volatile unsigned* vA = g_pA;
        volatile unsigned* vC = g_pC;
        volatile unsigned* vP = g_pP;
        unsigned a = 0, c = 0, p = 0;
        #pragma unroll
        for (int t2 = 0; t2 < TILES_PER_MASK; t2++) {
            int j = tid * TILES_PER_MASK + t2;
            a += vA[j]; c += vC[j]; p += vP[j];
        }
        float area  = (float)a;
        float conn  = (float)c;
        float perim = (float)p;

        float safe_area  = (area > 0.0f) ? area : 1.0f;
        float area_ratio = area / (float)(W * W);
        float area_score = (area_ratio >= 0.001f && area_ratio <= 0.5f) ? 1.0f : 0.1f;

        float comp_score = (conn > 0.0f)
            ? fminf(1.0f, 10.0f / (conn / safe_area + 1e-6f))
            : 0.1f;

        float par = perim / safe_area;
        float shape_score = (area > 0.0f)
            ? ((par <= 100.0f) ? 1.0f : fmaxf(0.1f, 100.0f / (par + 1e-6f)))
            : 0.1f;

        float validity = 0.4f * area_score + 0.3f * comp_score + 0.3f * shape_score;
        out[tid] = fmaxf(0.05f, validity);
    }
}

extern "C" void kernel_launch(void* const* d_in, const int* in_sizes, int n_in,
                              void* d_out, int out_size) {
    const float* masks = (const float*)d_in[0];
    float* out = (float*)d_out;
    (void)in_sizes; (void)n_in; (void)out_size;

    prior_kernel<<<NBLOCKS, 256>>>(masks, out);
}

// round 6
// speedup vs baseline: 2.7609x; 1.0025x over previous
#include <cuda_runtime.h>
#include <cuda_bf16.h>

#define NMASKS 128
#define W      1024
#define TILE_ROWS 62
#define TILES_PER_MASK 17                    // 16 x 62 rows + 1 x 32 rows
#define NTILES (NMASKS * TILES_PER_MASK)     // 2176
#define NPBLK  740                           // 148 SMs x 5 resident blocks
#define HALO_MAX 64                          // 62 + 2 -> exactly 8 iters/warp
#define STRIDE 35                            // gcd(35,32)=1 -> conflict-free

__device__ unsigned g_mA[NMASKS];            // zero-init; reset by last block
__device__ unsigned g_mC[NMASKS];
__device__ unsigned g_mP[NMASKS];
__device__ unsigned g_ticket = 0;            // reset by last block each launch
__device__ unsigned g_done = 0;              // atomicInc wrap -> self-resetting

__device__ __forceinline__ void csa(unsigned a, unsigned b, unsigned c,
                                    unsigned &s, unsigned &cy) {
    unsigned t = a ^ b;
    s  = t ^ c;
    cy = (a & b) | (t & c);
}

__global__ __launch_bounds__(256, 5)
void prior_kernel(const float* __restrict__ masks, float* __restrict__ out) {
    // Interleaved-bitplane packed rows. Group g (128 cols) occupies slots
    // 1+4g..4+4g: plane k bit l = column 128g + 4l + k.
    // Guard slot 0 == plane3 of group -1 (zero); slot 33 == plane0 of group 8.
    __shared__ unsigned srows[HALO_MAX][STRIDE];
    __shared__ unsigned red[8][3];
    __shared__ int cur_tile;
    __shared__ int is_last;

    const int tid  = threadIdx.x;
    const int lane = tid & 31;
    const int wp   = tid >> 5;               // 8 warps

    // guard words: zeroed once; pack never writes slots 33/34, and slot 0 is
    // only ever rewritten with 0 (out-of-image rows)
    for (int j = tid; j < HALO_MAX; j += 256) {
        srows[j][0] = 0u; srows[j][33] = 0u; srows[j][34] = 0u;
    }

    // ---- persistent loop: dynamic tile tickets ----
    while (true) {
        if (tid == 0) cur_tile = (int)atomicAdd(&g_ticket, 1u);
        __syncthreads();                     // publishes cur_tile; guards smem reuse
        const int t = cur_tile;
        if (t >= NTILES) break;

        const int mask = t / TILES_PER_MASK;
        const int tile = t - mask * TILES_PER_MASK;
        const int r0   = tile * TILE_ROWS;
        const int rows = (tile < 16) ? TILE_ROWS : (W - 16 * TILE_ROWS); // 62|32
        const int halo = rows + 2;
        const float4* __restrict__ base =
            (const float4*)(masks + (size_t)mask * (size_t)(W * W));

        // ---- pack: batched float4 loads (8 LDG.128 in flight), then ballots ----
        for (int k = wp; k < halo; k += 8) {
            int gr = r0 - 1 + k;
            if ((unsigned)gr >= (unsigned)W) {
                srows[k][lane] = 0u;
            } else {
                const float4* __restrict__ rowp = base + (size_t)gr * (W / 4);
                float4 v[8];
                #pragma unroll
                for (int it = 0; it < 8; it++) v[it] = rowp[it * 32 + lane];
                #pragma unroll
                for (int it = 0; it < 8; it++) {
                    unsigned p0 = __ballot_sync(0xffffffffu, v[it].x > 0.0f);
                    unsigned p1 = __ballot_sync(0xffffffffu, v[it].y > 0.0f);
                    unsigned p2 = __ballot_sync(0xffffffffu, v[it].z > 0.0f);
                    unsigned p3 = __ballot_sync(0xffffffffu, v[it].w > 0.0f);
                    unsigned mine = (lane == 0) ? p0 : (lane == 1) ? p1
                                  : (lane == 2) ? p2 : p3;
                    if (lane < 4) srows[k][1 + 4 * it + lane] = mine;
                }
            }
        }
        __syncthreads();

        // ---- compute: rows x 8 groups tasks over 256 threads ----
        unsigned accA = 0, accC = 0, accP = 0;
        const int ntasks = rows * 8;         // 496 or 256
        #pragma unroll 1
        for (int base_t = 0; base_t < ntasks; base_t += 256) {
            int id = tid + base_t;
            if (id >= ntasks) break;
            int g  = id & 7;
            int r  = id >> 3;
            const unsigned* __restrict__ Tr = srows[r];
            const unsigned* __restrict__ Mr = srows[r + 1];
            const unsigned* __restrict__ Br = srows[r + 2];
            int s = 1 + 4 * g;

            unsigned T[4], M[4], B[4];
            #pragma unroll
            for (int k = 0; k < 4; k++) { T[k] = Tr[s+k]; M[k] = Mr[s+k]; B[k] = Br[s+k]; }
            unsigned Tp3 = Tr[s-1], Mp3 = Mr[s-1], Bp3 = Br[s-1];
            unsigned Tn0 = Tr[s+4], Mn0 = Mr[s+4], Bn0 = Br[s+4];

            unsigned TSL = (T[3] << 1) | (Tp3 >> 31), TSR = (T[0] >> 1) | (Tn0 << 31);
            unsigned MSL = (M[3] << 1) | (Mp3 >> 31), MSR = (M[0] >> 1) | (Mn0 << 31);
            unsigned BSL = (B[3] << 1) | (Bp3 >> 31), BSR = (B[0] >> 1) | (Bn0 << 31);

            #pragma unroll
            for (int k = 0; k < 4; k++) {
                unsigned tl = (k > 0) ? T[k-1] : TSL;
                unsigned ml = (k > 0) ? M[k-1] : MSL;
                unsigned bl = (k > 0) ? B[k-1] : BSL;
                unsigned tr = (k < 3) ? T[k+1] : TSR;
                unsigned mr = (k < 3) ? M[k+1] : MSR;
                unsigned br = (k < 3) ? B[k+1] : BSR;
                unsigned tt = T[k], bot = B[k], mid = M[k];

                unsigned s1, c1, s2, c2, s3, c3;
                csa(tl, tt, tr, s1, c1);
                csa(ml, mr, bl, s2, c2);
                csa(bot, br, s1, s3, c3);
                unsigned s4 = s2 ^ s3, c4 = s2 & s3;
                unsigned u1, v1;
                csa(c1, c2, c3, u1, v1);
                unsigned u2 = u1 ^ c4, v2 = u1 & c4;
                unsigned b0 = s4, b1 = u2, b2 = v1 ^ v2, b3 = v1 & v2;

                accA += __popc(mid);

                unsigned conn = __popc(b0 & mid) + 2u * __popc(b1 & mid)
                              + 4u * __popc(b2 & mid) + 8u * __popc(b3 & mid);
                unsigned tot  = __popc(b0) + 2u * __popc(b1)
                              + 4u * __popc(b2) + 8u * __popc(b3);
                unsigned perim = (tot - conn)
                               + 4u * __popc(b3 & mid)
                               + 2u * __popc(b2 & b1 & mid)
                               +      __popc(b2 & b0 & mid);

                accC += conn;
                accP += perim;
            }
        }

        // ---- per-tile block reduction -> per-mask atomic accumulation ----
        accA = __reduce_add_sync(0xffffffffu, accA);
        accC = __reduce_add_sync(0xffffffffu, accC);
        accP = __reduce_add_sync(0xffffffffu, accP);
        if (lane == 0) { red[wp][0] = accA; red[wp][1] = accC; red[wp][2] = accP; }
        __syncthreads();
        if (tid == 0) {
            unsigned a = 0, c = 0, p = 0;
            #pragma unroll
            for (int w2 = 0; w2 < 8; w2++) { a += red[w2][0]; c += red[w2][1]; p += red[w2][2]; }
            atomicAdd(&g_mA[mask], a);
            atomicAdd(&g_mC[mask], c);
            atomicAdd(&g_mP[mask], p);
        }
        // loop-top __syncthreads() protects srows/red before next tile
    }

    // ---- completion: last finisher scores + resets state for graph replay ----
    if (tid == 0) {
        __threadfence();
        unsigned done = atomicInc(&g_done, NPBLK - 1);   // wraps to 0 itself
        is_last = (done == NPBLK - 1);
    }
    __syncthreads();

    if (is_last) {
        if (tid < NMASKS) {
            unsigned a = *(volatile unsigned*)&g_mA[tid];
            unsigned c = *(volatile unsigned*)&g_mC[tid];
            unsigned p = *(volatile unsigned*)&g_mP[tid];

            float area  = (float)a;
            float conn  = (float)c;
            float perim = (float)p;

            float safe_area  = (area > 0.0f) ? area : 1.0f;
            float area_ratio = area / (float)(W * W);
            float area_score = (area_ratio >= 0.001f && area_ratio <= 0.5f) ? 1.0f : 0.1f;

            float comp_score = (conn > 0.0f)
                ? fminf(1.0f, 10.0f / (conn / safe_area + 1e-6f))
                : 0.1f;

            float par = perim / safe_area;
            float shape_score = (area > 0.0f)
                ? ((par <= 100.0f) ? 1.0f : fmaxf(0.1f, 100.0f / (par + 1e-6f)))
                : 0.1f;

            float validity = 0.4f * area_score + 0.3f * comp_score + 0.3f * shape_score;
            out[tid] = fmaxf(0.05f, validity);

            // reset accumulators for the next graph replay
            g_mA[tid] = 0u; g_mC[tid] = 0u; g_mP[tid] = 0u;
        }
        if (tid == 0) g_ticket = 0u;
    }
}

extern "C" void kernel_launch(void* const* d_in, const int* in_sizes, int n_in,
                              void* d_out, int out_size) {
    const float* masks = (const float*)d_in[0];
    float* out = (float*)d_out;
    (void)in_sizes; (void)n_in; (void)out_size;

    prior_kernel<<<NPBLK, 256>>>(masks, out);
}